// round 1
// baseline (speedup 1.0000x reference)
#include <cuda_runtime.h>
#include <cuda_bf16.h>
#include <math.h>

// Problem constants
#define B   32
#define S   512
#define H   1024
#define T   37
#define LP  39
#define BS  (B*S)          // 16384
#define X3H (3*H)          // 3072

// Scratch (device-global; no runtime allocation allowed)
__device__ float g_X[BS * X3H];   // concat [h, aware, h*aware]  (192 MiB)
__device__ float g_Y[BS * H];     // gelu(x @ W_cat + b)          (64 MiB)

// ---------------------------------------------------------------------------
// Kernel 1: scores -> softmax -> aware -> X = [h, aware, h*aware]
// One block handles 32 rows; bio_embed staged in smem (37x1024 f32).
// ---------------------------------------------------------------------------
__global__ __launch_bounds__(256) void k1_bio_attn(
    const float* __restrict__ h, const float* __restrict__ bio)
{
    extern __shared__ float sm[];
    float* bioS  = sm;                 // 37*1024
    float* hS    = sm + T*H;           // 1024
    float* attnS = hS + H;             // 40

    int tid = threadIdx.x;

    // stage bio_embed (coalesced float4)
    {
        const float4* src = (const float4*)bio;
        float4* dst = (float4*)bioS;
        for (int i = tid; i < T*H/4; i += 256) dst[i] = src[i];
    }
    __syncthreads();

    int row0 = blockIdx.x * 32;
    int w = tid >> 5, l = tid & 31;

    for (int r = 0; r < 32; r++) {
        int row = row0 + r;
        // stage h row
        ((float4*)hS)[tid] = ((const float4*)(h + (size_t)row * H))[tid];
        __syncthreads();

        // scores: warp w handles t = w, w+8, ...
        #pragma unroll
        for (int i = 0; i < 5; i++) {
            int t = w + 8*i;
            if (t < T) {
                const float4* bt = (const float4*)(bioS + t*H);
                const float4* hv = (const float4*)hS;
                float s = 0.f;
                for (int k = l; k < H/4; k += 32) {
                    float4 a = hv[k], b4 = bt[k];
                    s += a.x*b4.x + a.y*b4.y + a.z*b4.z + a.w*b4.w;
                }
                #pragma unroll
                for (int o = 16; o; o >>= 1) s += __shfl_xor_sync(~0u, s, o);
                if (l == 0) attnS[t] = s * 0.03125f;   // 1/sqrt(1024)
            }
        }
        __syncthreads();

        // softmax over 37 (warp 0)
        if (tid < 32) {
            float v0 = attnS[tid];
            float v1 = (tid < T-32) ? attnS[32+tid] : -1e30f;
            float m = fmaxf(v0, v1);
            #pragma unroll
            for (int o = 16; o; o >>= 1) m = fmaxf(m, __shfl_xor_sync(~0u, m, o));
            float e0 = __expf(v0 - m);
            float e1 = (tid < T-32) ? __expf(v1 - m) : 0.f;
            float ss = e0 + e1;
            #pragma unroll
            for (int o = 16; o; o >>= 1) ss += __shfl_xor_sync(~0u, ss, o);
            float inv = 1.f / ss;
            attnS[tid] = e0 * inv;
            if (tid < T-32) attnS[32+tid] = e1 * inv;
        }
        __syncthreads();

        // aware + write X
        float4 hv = ((float4*)hS)[tid];
        float4 acc = make_float4(0.f,0.f,0.f,0.f);
        #pragma unroll 1
        for (int t = 0; t < T; t++) {
            float a = attnS[t];
            float4 bv = ((float4*)(bioS + t*H))[tid];
            acc.x += a*bv.x; acc.y += a*bv.y; acc.z += a*bv.z; acc.w += a*bv.w;
        }
        float* xr = g_X + (size_t)row * X3H;
        ((float4*)xr)[tid] = hv;
        ((float4*)(xr + H))[tid] = acc;
        float4 pr = make_float4(hv.x*acc.x, hv.y*acc.y, hv.z*acc.z, hv.w*acc.w);
        ((float4*)(xr + 2*H))[tid] = pr;
        __syncthreads();
    }
}

// ---------------------------------------------------------------------------
// Kernel 2: Y = gelu(X @ W_cat + b_cat)   [16384,3072] @ [3072,1024]
// Classic 128x128x8 SGEMM, 256 threads, 8x8 per thread.
// ---------------------------------------------------------------------------
#define BM 128
#define BN 128
#define BKk 8
__global__ __launch_bounds__(256) void k2_gemm_gelu(
    const float* __restrict__ Wc, const float* __restrict__ bc)
{
    __shared__ float As[BKk][BM];
    __shared__ float Bs[BKk][BN];

    int tid = threadIdx.x;
    int bx = blockIdx.x;   // N tile (0..7)
    int by = blockIdx.y;   // M tile (0..127)

    int tx = tid % 16, ty = tid / 16;

    const float* Ab = g_X + (size_t)by * BM * X3H;
    const float* Bb = Wc + bx * BN;

    float acc[8][8];
    #pragma unroll
    for (int i = 0; i < 8; i++)
        #pragma unroll
        for (int j = 0; j < 8; j++) acc[i][j] = 0.f;

    int aRow = tid >> 1, aCol = (tid & 1) * 4;   // 128x8 via float4
    int bRow = tid >> 5, bCol = (tid & 31) * 4;  // 8x128 via float4

    for (int k0 = 0; k0 < X3H; k0 += BKk) {
        float4 av = *(const float4*)(Ab + (size_t)aRow * X3H + k0 + aCol);
        As[aCol+0][aRow] = av.x; As[aCol+1][aRow] = av.y;
        As[aCol+2][aRow] = av.z; As[aCol+3][aRow] = av.w;
        float4 bv = *(const float4*)(Bb + (size_t)(k0 + bRow) * H + bCol);
        *(float4*)(&Bs[bRow][bCol]) = bv;
        __syncthreads();

        #pragma unroll
        for (int kk = 0; kk < BKk; kk++) {
            float ar[8], br[8];
            #pragma unroll
            for (int i = 0; i < 8; i++) ar[i] = As[kk][ty*8 + i];
            #pragma unroll
            for (int j = 0; j < 8; j++) br[j] = Bs[kk][tx*8 + j];
            #pragma unroll
            for (int i = 0; i < 8; i++)
                #pragma unroll
                for (int j = 0; j < 8; j++)
                    acc[i][j] += ar[i] * br[j];
        }
        __syncthreads();
    }

    // epilogue: bias + exact GELU, store Y
    #pragma unroll
    for (int i = 0; i < 8; i++) {
        int row = by*BM + ty*8 + i;
        float* yr = g_Y + (size_t)row * H + bx*BN + tx*8;
        #pragma unroll
        for (int j = 0; j < 8; j++) {
            float v = acc[i][j] + bc[bx*BN + tx*8 + j];
            v = 0.5f * v * (1.f + erff(v * 0.70710678118654752f));
            yr[j] = v;
        }
    }
}

// ---------------------------------------------------------------------------
// Kernel 3: logits = Y @ W_crf + b_crf, write ner_scores (with -10000 pads)
// W_crf staged transposed in smem (pitch 1028 for f4 alignment).
// One block handles 64 rows.
// ---------------------------------------------------------------------------
#define WPITCH 1028
__global__ __launch_bounds__(256) void k3_crf_proj(
    const float* __restrict__ Wc, const float* __restrict__ bc,
    float* __restrict__ out)
{
    extern __shared__ float sm[];
    float* Ws = sm;               // 37*1028
    float* Ys = sm + T*WPITCH;    // 1024

    int tid = threadIdx.x;
    for (int idx = tid; idx < H*T; idx += 256) {
        int k = idx / T, t = idx % T;
        Ws[t*WPITCH + k] = Wc[idx];
    }
    __syncthreads();

    int row0 = blockIdx.x * 64;
    int w = tid >> 5, l = tid & 31;

    for (int r = 0; r < 64; r++) {
        int row = row0 + r;
        ((float4*)Ys)[tid] = ((const float4*)(g_Y + (size_t)row * H))[tid];
        __syncthreads();

        #pragma unroll
        for (int i = 0; i < 5; i++) {
            int t = w + 8*i;
            if (t < T) {
                const float4* wv = (const float4*)(Ws + t*WPITCH);
                const float4* yv = (const float4*)Ys;
                float s = 0.f;
                for (int k = l; k < H/4; k += 32) {
                    float4 a = yv[k], b4 = wv[k];
                    s += a.x*b4.x + a.y*b4.y + a.z*b4.z + a.w*b4.w;
                }
                #pragma unroll
                for (int o = 16; o; o >>= 1) s += __shfl_xor_sync(~0u, s, o);
                if (l == 0) out[(size_t)row*LP + t] = s + bc[t];
            }
        }
        if (tid == 0) {
            out[(size_t)row*LP + 37] = -10000.f;
            out[(size_t)row*LP + 38] = -10000.f;
        }
        __syncthreads();
    }
}

// ---------------------------------------------------------------------------
// Kernel 4: CRF log-likelihood. One block per batch element, 64 threads.
// Scan step recast: precompute ET[to][frm] = exp(trans - rowmax(trans)),
// then alpha'[to] = logit[to] + A + maxT[to] + log( sum_frm e[frm]*ET[frm] )
// with e[frm] = exp(alpha[frm] - A), A = max(alpha). Exact logsumexp.
// ---------------------------------------------------------------------------
__global__ __launch_bounds__(64) void k4_crf(
    const float* __restrict__ scores,   // d_out ner_scores [B,S,LP]
    const int* __restrict__ labels, const int* __restrict__ lens,
    const float* __restrict__ trans, float* __restrict__ loss)
{
    extern __shared__ float sm[];
    float* sc = sm;                 // S*LP = 19968 floats
    __shared__ float alpha[40];
    __shared__ float evec[40];
    __shared__ float redm[4];

    int b = blockIdx.x;
    int tid = threadIdx.x;
    int len = lens[b];
    const int* lab = labels + b*S;

    // stage this batch's scores
    {
        const float4* src = (const float4*)(scores + (size_t)b * S * LP);
        float4* dst = (float4*)sc;
        for (int i = tid; i < S*LP/4; i += 64) dst[i] = src[i];
    }

    // per-thread ET row (thread i owns "to" = i)
    float ET[LP];
    float maxT = -1e30f;
    if (tid < LP) {
        const float* tr = trans + tid*LP;
        #pragma unroll
        for (int f = 0; f < LP; f++) maxT = fmaxf(maxT, tr[f]);
        #pragma unroll
        for (int f = 0; f < LP; f++) ET[f] = __expf(tr[f] - maxT);
    }
    __syncthreads();

    // gold score
    float g = 0.f;
    for (int s = tid; s < len; s += 64) g += sc[s*LP + lab[s]];
    for (int i = tid; i <= len; i += 64) {
        int frm = (i == 0)   ? (T)     : lab[i-1];   // START=37
        int to  = (i == len) ? (T + 1) : lab[i];     // END=38
        g += trans[to*LP + frm];
    }
    #pragma unroll
    for (int o = 16; o; o >>= 1) g += __shfl_xor_sync(~0u, g, o);
    if ((tid & 31) == 0) redm[2 + (tid >> 5)] = g;

    // init alpha
    if (tid < LP) alpha[tid] = (tid == T) ? 0.f : -100.f;
    __syncthreads();
    float gold = redm[2] + redm[3];

    for (int t = 0; t < len; t++) {
        float v = (tid < LP) ? alpha[tid] : -1e30f;
        #pragma unroll
        for (int o = 16; o; o >>= 1) v = fmaxf(v, __shfl_xor_sync(~0u, v, o));
        if ((tid & 31) == 0) redm[tid >> 5] = v;
        __syncthreads();
        float A = fmaxf(redm[0], redm[1]);
        if (tid < LP) evec[tid] = __expf(alpha[tid] - A);
        __syncthreads();
        float anew = 0.f;
        if (tid < LP) {
            float s2 = 0.f;
            #pragma unroll
            for (int f = 0; f < LP; f++) s2 += evec[f] * ET[f];
            anew = sc[t*LP + tid] + A + maxT + __logf(s2);
        }
        __syncthreads();
        if (tid < LP) alpha[tid] = anew;
        __syncthreads();
    }

    // norm = LSE(alpha + trans[END][:])
    if (tid < LP) alpha[tid] += trans[(T+1)*LP + tid];
    __syncthreads();
    float v = (tid < LP) ? alpha[tid] : -1e30f;
    #pragma unroll
    for (int o = 16; o; o >>= 1) v = fmaxf(v, __shfl_xor_sync(~0u, v, o));
    if ((tid & 31) == 0) redm[tid >> 5] = v;
    __syncthreads();
    float A = fmaxf(redm[0], redm[1]);
    float e = (tid < LP) ? __expf(alpha[tid] - A) : 0.f;
    #pragma unroll
    for (int o = 16; o; o >>= 1) e += __shfl_xor_sync(~0u, e, o);
    if ((tid & 31) == 0) redm[2 + (tid >> 5)] = e;
    __syncthreads();
    if (tid == 0) {
        float norm = A + logf(redm[2] + redm[3]);
        loss[b] = gold - norm;
    }
}

// ---------------------------------------------------------------------------
extern "C" void kernel_launch(void* const* d_in, const int* in_sizes, int n_in,
                              void* d_out, int out_size)
{
    const float* h      = (const float*)d_in[0];
    // d_in[1] = token_masks (unused; all work derives from token_nums)
    const int*   lens   = (const int*)d_in[2];
    const int*   labels = (const int*)d_in[3];
    const float* bio    = (const float*)d_in[4];
    const float* W_cat  = (const float*)d_in[5];
    const float* b_cat  = (const float*)d_in[6];
    const float* W_crf  = (const float*)d_in[7];
    const float* b_crf  = (const float*)d_in[8];
    const float* trans  = (const float*)d_in[9];

    float* out = (float*)d_out;            // ner_scores [B,S,LP] then loss [B]
    float* loss = out + (size_t)B * S * LP;

    size_t smem1 = (size_t)(T*H + H + 64) * sizeof(float);
    size_t smem3 = (size_t)(T*WPITCH + H + 16) * sizeof(float);
    size_t smem4 = (size_t)(S*LP) * sizeof(float);

    static int attr_done = 0;
    if (!attr_done) {
        cudaFuncSetAttribute(k1_bio_attn, cudaFuncAttributeMaxDynamicSharedMemorySize, (int)smem1);
        cudaFuncSetAttribute(k3_crf_proj, cudaFuncAttributeMaxDynamicSharedMemorySize, (int)smem3);
        cudaFuncSetAttribute(k4_crf,      cudaFuncAttributeMaxDynamicSharedMemorySize, (int)smem4);
        attr_done = 1;
    }

    k1_bio_attn<<<BS/32, 256, smem1>>>(h, bio);
    dim3 g2(H/BN, BS/BM);
    k2_gemm_gelu<<<g2, 256>>>(W_cat, b_cat);
    k3_crf_proj<<<BS/64, 256, smem3>>>(W_crf, b_crf, out);
    k4_crf<<<B, 64, smem4>>>(out, labels, lens, trans, loss);
}

// round 3
// speedup vs baseline: 2.0798x; 2.0798x over previous
#include <cuda_runtime.h>
#include <cuda_bf16.h>
#include <cstdint>
#include <math.h>

// Problem constants
#define B   32
#define S   512
#define H   1024
#define T   37
#define LP  39
#define BS  (B*S)          // 16384
#define ZK  2048           // reduced K: [h, h*aware]

// Scratch (device-global)
__device__ float g_Z[BS * ZK];     // [h, h*aware], tf32-rounded   (128 MiB)
__device__ float g_Wp[ZK * H];     // [W1; W3] tf32-rounded        (8 MiB)
__device__ float g_Y[BS * H];      // gelu output                  (64 MiB)
__device__ float g_P[BS * H];      // b_cat + attn @ (bio@W2)      (64 MiB)
__device__ float g_attn[BS * T];   // softmax attn                 (2.4 MiB)
__device__ float g_BW2[T * H];     // bio_embed @ W2               (148 KiB)

// ===========================================================================
// helpers
// ===========================================================================
__device__ __forceinline__ uint32_t smem_u32(const void* p) {
    uint32_t a;
    asm("{ .reg .u64 t; cvta.to.shared.u64 t, %1; cvt.u32.u64 %0, t; }"
        : "=r"(a) : "l"(p));
    return a;
}
__device__ __forceinline__ void cp16(uint32_t dst, const void* src) {
    asm volatile("cp.async.cg.shared.global [%0], [%1], 16;\n" :: "r"(dst), "l"(src));
}
#define CP_COMMIT() asm volatile("cp.async.commit_group;\n" ::: "memory")
#define CP_WAIT(n)  asm volatile("cp.async.wait_group %0;\n" :: "n"(n) : "memory")

__device__ __forceinline__ float tf32r(float x) {
    uint32_t u;
    asm("cvt.rna.tf32.f32 %0, %1;" : "=r"(u) : "f"(x));
    return __uint_as_float(u);
}
__device__ __forceinline__ float gelu(float v) {
    return 0.5f * v * (1.f + erff(v * 0.70710678118654752f));
}

// ---------------------------------------------------------------------------
// prep A: g_Wp = tf32([W1; W3])   (W_cat rows 0..1023 and 2048..3071)
// ---------------------------------------------------------------------------
__global__ __launch_bounds__(256) void kprep_w(const float* __restrict__ W)
{
    int r = blockIdx.x;                   // 0..2047
    int src = (r < H) ? r : (r + H);      // skip W2 block
    const float4* s = (const float4*)(W + (size_t)src * H);
    float4* d = (float4*)(g_Wp + (size_t)r * H);
    float4 v = s[threadIdx.x];
    d[threadIdx.x] = make_float4(tf32r(v.x), tf32r(v.y), tf32r(v.z), tf32r(v.w));
}

// ---------------------------------------------------------------------------
// g_BW2[t][n] = sum_k bio[t][k] * W_cat[1024+k][n]
// ---------------------------------------------------------------------------
__global__ __launch_bounds__(256) void k_bw2(
    const float* __restrict__ bio, const float* __restrict__ W)
{
    int n = blockIdx.x * 256 + threadIdx.x;
    int t = blockIdx.y;
    const float* br = bio + (size_t)t * H;
    float acc = 0.f;
    #pragma unroll 8
    for (int k = 0; k < H; k++)
        acc += br[k] * W[(size_t)(H + k) * H + n];
    g_BW2[t * H + n] = acc;
}

// ---------------------------------------------------------------------------
// Kernel 1: scores -> softmax -> attn, aware; write Z=[tf32(h), tf32(h*aware)]
// ---------------------------------------------------------------------------
__global__ __launch_bounds__(256) void k1_bio_attn(
    const float* __restrict__ h, const float* __restrict__ bio)
{
    extern __shared__ float sm[];
    float* bioS  = sm;                 // 37*1024
    float* hS    = sm + T*H;           // 1024
    float* attnS = hS + H;             // 40

    int tid = threadIdx.x;
    {
        const float4* src = (const float4*)bio;
        float4* dst = (float4*)bioS;
        for (int i = tid; i < T*H/4; i += 256) dst[i] = src[i];
    }
    __syncthreads();

    int row0 = blockIdx.x * 32;
    int w = tid >> 5, l = tid & 31;

    for (int r = 0; r < 32; r++) {
        int row = row0 + r;
        ((float4*)hS)[tid] = ((const float4*)(h + (size_t)row * H))[tid];
        __syncthreads();

        #pragma unroll
        for (int i = 0; i < 5; i++) {
            int t = w + 8*i;
            if (t < T) {
                const float4* bt = (const float4*)(bioS + t*H);
                const float4* hv = (const float4*)hS;
                float s = 0.f;
                for (int k = l; k < H/4; k += 32) {
                    float4 a = hv[k], b4 = bt[k];
                    s += a.x*b4.x + a.y*b4.y + a.z*b4.z + a.w*b4.w;
                }
                #pragma unroll
                for (int o = 16; o; o >>= 1) s += __shfl_xor_sync(~0u, s, o);
                if (l == 0) attnS[t] = s * 0.03125f;
            }
        }
        __syncthreads();

        if (tid < 32) {
            float v0 = attnS[tid];
            float v1 = (tid < T-32) ? attnS[32+tid] : -1e30f;
            float m = fmaxf(v0, v1);
            #pragma unroll
            for (int o = 16; o; o >>= 1) m = fmaxf(m, __shfl_xor_sync(~0u, m, o));
            float e0 = __expf(v0 - m);
            float e1 = (tid < T-32) ? __expf(v1 - m) : 0.f;
            float ss = e0 + e1;
            #pragma unroll
            for (int o = 16; o; o >>= 1) ss += __shfl_xor_sync(~0u, ss, o);
            float inv = 1.f / ss;
            attnS[tid] = e0 * inv;
            if (tid < T-32) attnS[32+tid] = e1 * inv;
        }
        __syncthreads();

        if (tid < T) g_attn[(size_t)row * T + tid] = attnS[tid];

        float4 hv = ((float4*)hS)[tid];
        float4 acc = make_float4(0.f,0.f,0.f,0.f);
        #pragma unroll 1
        for (int t = 0; t < T; t++) {
            float a = attnS[t];
            float4 bv = ((float4*)(bioS + t*H))[tid];
            acc.x += a*bv.x; acc.y += a*bv.y; acc.z += a*bv.z; acc.w += a*bv.w;
        }
        float* zr = g_Z + (size_t)row * ZK;
        ((float4*)zr)[tid] = make_float4(tf32r(hv.x), tf32r(hv.y), tf32r(hv.z), tf32r(hv.w));
        ((float4*)(zr + H))[tid] = make_float4(tf32r(hv.x*acc.x), tf32r(hv.y*acc.y),
                                               tf32r(hv.z*acc.z), tf32r(hv.w*acc.w));
        __syncthreads();
    }
}

// ---------------------------------------------------------------------------
// k_pre: g_P[row][:] = b_cat + attn[row] @ g_BW2      (K=37, memory-bound)
// ---------------------------------------------------------------------------
__global__ __launch_bounds__(256) void k_pre(const float* __restrict__ bc)
{
    extern __shared__ float sm[];
    float* bw = sm;            // 37*1024
    float* ar = sm + T*H;      // 40

    int tid = threadIdx.x;
    {
        const float4* src = (const float4*)g_BW2;
        float4* dst = (float4*)bw;
        for (int i = tid; i < T*H/4; i += 256) dst[i] = src[i];
    }
    float4 bc4 = ((const float4*)bc)[tid];
    __syncthreads();

    int row0 = blockIdx.x * 64;
    for (int r = 0; r < 64; r++) {
        int row = row0 + r;
        if (tid < T) ar[tid] = g_attn[(size_t)row * T + tid];
        __syncthreads();
        float4 acc = bc4;
        #pragma unroll 1
        for (int t = 0; t < T; t++) {
            float a = ar[t];
            float4 wv = ((const float4*)(bw + t*H))[tid];
            acc.x += a*wv.x; acc.y += a*wv.y; acc.z += a*wv.z; acc.w += a*wv.w;
        }
        ((float4*)(g_P + (size_t)row * H))[tid] = acc;
        __syncthreads();
    }
}

// ---------------------------------------------------------------------------
// Kernel 2: Y = gelu(Z @ Wp + P) via mma.sync tf32
// BM=128, BN=128, BK=32, 4 stages, 8 warps (4x2), warp tile 32x64.
// ---------------------------------------------------------------------------
#define KBM 128
#define KBN 128
#define KBK 32
#define KITER (ZK/KBK)            // 64
#define PA 36                     // A smem pitch (floats), ≡4 mod 32
#define PB 136                    // B smem pitch (floats), ≡8 mod 32
#define A_BYTES (KBM*PA*4)        // 18432
#define B_BYTES (KBK*PB*4)        // 17408
#define STG_BYTES (A_BYTES + B_BYTES)   // 35840
#define STG_FLOATS (STG_BYTES/4)        // 8960
#define SMEM_K2 (4*STG_BYTES)           // 143360

__device__ __forceinline__ void mma_tf32(
    float* d, const uint32_t* a, uint32_t b0, uint32_t b1)
{
    asm volatile(
        "mma.sync.aligned.m16n8k8.row.col.f32.tf32.tf32.f32 "
        "{%0,%1,%2,%3}, {%4,%5,%6,%7}, {%8,%9}, {%0,%1,%2,%3};"
        : "+f"(d[0]), "+f"(d[1]), "+f"(d[2]), "+f"(d[3])
        : "r"(a[0]), "r"(a[1]), "r"(a[2]), "r"(a[3]), "r"(b0), "r"(b1));
}

__device__ __forceinline__ void k2_load_stage(
    uint32_t sbase, int tid, int j, const float* Zb, const float* Wb)
{
    uint32_t sa = sbase + (j & 3) * STG_BYTES;
    int ktile = j * KBK;
    #pragma unroll
    for (int q = 0; q < 8; q++) {
        int idx = tid + 256*q;
        if (q < 4) {
            int m = idx >> 3, c = idx & 7;
            cp16(sa + m*144 + c*16, Zb + (size_t)m * ZK + ktile + c*4);
        } else {
            int ci = idx - 1024;
            int k = ci >> 5, c = ci & 31;
            cp16(sa + A_BYTES + k*544 + c*16, Wb + (size_t)(ktile + k) * H + c*4);
        }
    }
}

__global__ __launch_bounds__(256, 1) void k2_mma()
{
    extern __shared__ __align__(16) float sm[];
    uint32_t sbase = smem_u32(sm);
    int tid = threadIdx.x;
    int wid = tid >> 5, lane = tid & 31;
    int g = lane >> 2, t = lane & 3;
    int wm = wid & 3, wn = wid >> 2;          // 4 x 2 warp grid
    int row0 = blockIdx.y * KBM;
    int n0   = blockIdx.x * KBN;

    const float* Zb = g_Z  + (size_t)row0 * ZK;
    const float* Wb = g_Wp + n0;

    float acc[2][8][4];
    #pragma unroll
    for (int mt = 0; mt < 2; mt++)
        #pragma unroll
        for (int nt = 0; nt < 8; nt++)
            #pragma unroll
            for (int q = 0; q < 4; q++) acc[mt][nt][q] = 0.f;

    #pragma unroll
    for (int s2 = 0; s2 < 3; s2++) { k2_load_stage(sbase, tid, s2, Zb, Wb); CP_COMMIT(); }

    for (int i = 0; i < KITER; i++) {
        int j = i + 3;
        if (j < KITER) k2_load_stage(sbase, tid, j, Zb, Wb);
        CP_COMMIT();
        CP_WAIT(3);
        __syncthreads();

        const float* As = sm + (i & 3) * STG_FLOATS;
        const float* Bs = As + A_BYTES/4;
        #pragma unroll
        for (int kk = 0; kk < 4; kk++) {
            int k0 = kk * 8;
            uint32_t a[2][4];
            #pragma unroll
            for (int mt = 0; mt < 2; mt++) {
                int mb = wm*32 + mt*16 + g;
                a[mt][0] = __float_as_uint(As[mb*PA + k0 + t]);
                a[mt][1] = __float_as_uint(As[(mb+8)*PA + k0 + t]);
                a[mt][2] = __float_as_uint(As[mb*PA + k0 + t + 4]);
                a[mt][3] = __float_as_uint(As[(mb+8)*PA + k0 + t + 4]);
            }
            #pragma unroll
            for (int nt = 0; nt < 8; nt++) {
                int nb = wn*64 + nt*8 + g;
                uint32_t b0 = __float_as_uint(Bs[(k0+t)*PB + nb]);
                uint32_t b1 = __float_as_uint(Bs[(k0+t+4)*PB + nb]);
                #pragma unroll
                for (int mt = 0; mt < 2; mt++) mma_tf32(acc[mt][nt], a[mt], b0, b1);
            }
        }
        __syncthreads();
    }

    // epilogue: += P, gelu, store
    #pragma unroll
    for (int mt = 0; mt < 2; mt++) {
        #pragma unroll
        for (int nt = 0; nt < 8; nt++) {
            int r0 = row0 + wm*32 + mt*16 + g;
            int c  = n0 + wn*64 + nt*8 + t*2;
            #pragma unroll
            for (int half = 0; half < 2; half++) {
                int r = r0 + half*8;
                const float2 p = *(const float2*)(g_P + (size_t)r * H + c);
                float2 o;
                o.x = gelu(acc[mt][nt][half*2 + 0] + p.x);
                o.y = gelu(acc[mt][nt][half*2 + 1] + p.y);
                *(float2*)(g_Y + (size_t)r * H + c) = o;
            }
        }
    }
}

// ---------------------------------------------------------------------------
// Kernel 3: logits = Y @ W_crf + b_crf -> ner_scores (+ -10000 pads)
// ---------------------------------------------------------------------------
#define WPITCH 1028
__global__ __launch_bounds__(256) void k3_crf_proj(
    const float* __restrict__ Wc, const float* __restrict__ bc,
    float* __restrict__ out)
{
    extern __shared__ float sm[];
    float* Ws = sm;               // 37*1028
    float* Ys = sm + T*WPITCH;    // 1024

    int tid = threadIdx.x;
    for (int idx = tid; idx < H*T; idx += 256) {
        int k = idx / T, t = idx % T;
        Ws[t*WPITCH + k] = Wc[idx];
    }
    __syncthreads();

    int row0 = blockIdx.x * 64;
    int w = tid >> 5, l = tid & 31;

    for (int r = 0; r < 64; r++) {
        int row = row0 + r;
        ((float4*)Ys)[tid] = ((const float4*)(g_Y + (size_t)row * H))[tid];
        __syncthreads();

        #pragma unroll
        for (int i = 0; i < 5; i++) {
            int t = w + 8*i;
            if (t < T) {
                const float4* wv = (const float4*)(Ws + t*WPITCH);
                const float4* yv = (const float4*)Ys;
                float s = 0.f;
                for (int k = l; k < H/4; k += 32) {
                    float4 a = yv[k], b4 = wv[k];
                    s += a.x*b4.x + a.y*b4.y + a.z*b4.z + a.w*b4.w;
                }
                #pragma unroll
                for (int o = 16; o; o >>= 1) s += __shfl_xor_sync(~0u, s, o);
                if (l == 0) out[(size_t)row*LP + t] = s + bc[t];
            }
        }
        if (tid == 0) {
            out[(size_t)row*LP + 37] = -10000.f;
            out[(size_t)row*LP + 38] = -10000.f;
        }
        __syncthreads();
    }
}

// ---------------------------------------------------------------------------
// Kernel 4: CRF loglik. One warp per batch; shuffle-only scan.
// ---------------------------------------------------------------------------
__global__ __launch_bounds__(32) void k4_crf(
    const float* __restrict__ scores, const int* __restrict__ labels,
    const int* __restrict__ lens, const float* __restrict__ trans,
    float* __restrict__ loss)
{
    extern __shared__ float sc[];   // S*LP floats
    int b = blockIdx.x;
    int lane = threadIdx.x;
    int len = lens[b];
    const int* lab = labels + b*S;

    {
        uint32_t sbase = smem_u32(sc);
        const float4* src = (const float4*)(scores + (size_t)b * S * LP);
        for (int i = lane; i < S*LP/4; i += 32)
            cp16(sbase + i*16, src + i);
        CP_COMMIT();
        CP_WAIT(0);
        __syncwarp();
    }

    float ET0[LP], ET1[LP], maxT0 = -1e30f, maxT1 = -1e30f;
    {
        const float* tr = trans + lane*LP;
        #pragma unroll
        for (int f = 0; f < LP; f++) maxT0 = fmaxf(maxT0, tr[f]);
        #pragma unroll
        for (int f = 0; f < LP; f++) ET0[f] = __expf(tr[f] - maxT0);
    }
    if (lane < LP-32) {
        const float* tr = trans + (32+lane)*LP;
        #pragma unroll
        for (int f = 0; f < LP; f++) maxT1 = fmaxf(maxT1, tr[f]);
        #pragma unroll
        for (int f = 0; f < LP; f++) ET1[f] = __expf(tr[f] - maxT1);
    }

    float g = 0.f;
    for (int s2 = lane; s2 < len; s2 += 32) g += sc[s2*LP + lab[s2]];
    for (int i = lane; i <= len; i += 32) {
        int frm = (i == 0)   ? T       : lab[i-1];
        int to  = (i == len) ? (T + 1) : lab[i];
        g += trans[to*LP + frm];
    }
    #pragma unroll
    for (int o = 16; o; o >>= 1) g += __shfl_xor_sync(~0u, g, o);

    float a0 = -100.f;
    float a1 = (lane == (T - 32)) ? 0.f : -100.f;

    for (int t = 0; t < len; t++) {
        float v = fmaxf(a0, (lane < LP-32) ? a1 : -1e30f);
        #pragma unroll
        for (int o = 16; o; o >>= 1) v = fmaxf(v, __shfl_xor_sync(~0u, v, o));
        float e0 = __expf(a0 - v);
        float e1 = (lane < LP-32) ? __expf(a1 - v) : 0.f;
        float s0a = 0.f, s0b = 0.f, s1a = 0.f, s1b = 0.f;
        #pragma unroll
        for (int f = 0; f < 32; f += 2) {
            float ea = __shfl_sync(~0u, e0, f);
            float eb = __shfl_sync(~0u, e0, f+1);
            s0a += ea*ET0[f];   s0b += eb*ET0[f+1];
            s1a += ea*ET1[f];   s1b += eb*ET1[f+1];
        }
        #pragma unroll
        for (int f = 0; f < LP-32; f++) {
            float ea = __shfl_sync(~0u, e1, f);
            s0a += ea*ET0[32+f];
            s1a += ea*ET1[32+f];
        }
        a0 = sc[t*LP + lane] + v + maxT0 + __logf(s0a + s0b);
        if (lane < LP-32)
            a1 = sc[t*LP + 32 + lane] + v + maxT1 + __logf(s1a + s1b);
    }

    a0 += trans[(T+1)*LP + lane];
    if (lane < LP-32) a1 += trans[(T+1)*LP + 32 + lane];
    float v = fmaxf(a0, (lane < LP-32) ? a1 : -1e30f);
    #pragma unroll
    for (int o = 16; o; o >>= 1) v = fmaxf(v, __shfl_xor_sync(~0u, v, o));
    float e = __expf(a0 - v) + ((lane < LP-32) ? __expf(a1 - v) : 0.f);
    #pragma unroll
    for (int o = 16; o; o >>= 1) e += __shfl_xor_sync(~0u, e, o);
    if (lane == 0) loss[b] = g - (v + logf(e));
}

// ---------------------------------------------------------------------------
extern "C" void kernel_launch(void* const* d_in, const int* in_sizes, int n_in,
                              void* d_out, int out_size)
{
    const float* h      = (const float*)d_in[0];
    const int*   lens   = (const int*)d_in[2];
    const int*   labels = (const int*)d_in[3];
    const float* bio    = (const float*)d_in[4];
    const float* W_cat  = (const float*)d_in[5];
    const float* b_cat  = (const float*)d_in[6];
    const float* W_crf  = (const float*)d_in[7];
    const float* b_crf  = (const float*)d_in[8];
    const float* trans  = (const float*)d_in[9];

    float* out = (float*)d_out;            // ner_scores [B,S,LP] then loss [B]
    float* loss = out + (size_t)B * S * LP;

    size_t smem1 = (size_t)(T*H + H + 64) * sizeof(float);
    size_t smemP = (size_t)(T*H + 64) * sizeof(float);
    size_t smem3 = (size_t)(T*WPITCH + H + 16) * sizeof(float);
    size_t smem4 = (size_t)(S*LP) * sizeof(float);

    static int attr_done = 0;
    if (!attr_done) {
        cudaFuncSetAttribute(k1_bio_attn, cudaFuncAttributeMaxDynamicSharedMemorySize, (int)smem1);
        cudaFuncSetAttribute(k_pre,       cudaFuncAttributeMaxDynamicSharedMemorySize, (int)smemP);
        cudaFuncSetAttribute(k2_mma,      cudaFuncAttributeMaxDynamicSharedMemorySize, SMEM_K2);
        cudaFuncSetAttribute(k3_crf_proj, cudaFuncAttributeMaxDynamicSharedMemorySize, (int)smem3);
        cudaFuncSetAttribute(k4_crf,      cudaFuncAttributeMaxDynamicSharedMemorySize, (int)smem4);
        attr_done = 1;
    }

    kprep_w<<<ZK, 256>>>(W_cat);
    k_bw2<<<dim3(H/256, T), 256>>>(bio, W_cat);
    k1_bio_attn<<<BS/32, 256, smem1>>>(h, bio);
    k_pre<<<BS/64, 256, smemP>>>(b_cat);
    k2_mma<<<dim3(H/KBN, BS/KBM), 256, SMEM_K2>>>();
    k3_crf_proj<<<BS/64, 256, smem3>>>(W_crf, b_crf, out);
    k4_crf<<<B, 32, smem4>>>(out, labels, lens, trans, loss);
}

// round 4
// speedup vs baseline: 4.5558x; 2.1905x over previous
#include <cuda_runtime.h>
#include <cuda_bf16.h>
#include <cstdint>
#include <math.h>

// Problem constants
#define B   32
#define S   512
#define H   1024
#define T   37
#define LP  39
#define BS  (B*S)          // 16384
#define ZK2 2112           // 1024 (h) + 1024 (h*aware) + 64 (attn, 37 used)

// Scratch (device-global, zero-initialized at module load)
__device__ __align__(256) __nv_bfloat16 g_Zb[BS * ZK2];  // 66 MiB
__device__ __align__(256) __nv_bfloat16 g_Wt[H * ZK2];   // [n][k]  4.3 MiB
__device__ __align__(256) float g_Y[BS * H];             // 64 MiB

// ===========================================================================
// helpers
// ===========================================================================
__device__ __forceinline__ uint32_t smem_u32(const void* p) {
    uint32_t a;
    asm("{ .reg .u64 t; cvta.to.shared.u64 t, %1; cvt.u32.u64 %0, t; }"
        : "=r"(a) : "l"(p));
    return a;
}
__device__ __forceinline__ void cp16(uint32_t dst, const void* src) {
    asm volatile("cp.async.cg.shared.global [%0], [%1], 16;\n" :: "r"(dst), "l"(src));
}
#define CP_COMMIT() asm volatile("cp.async.commit_group;\n" ::: "memory")
#define CP_WAIT(n)  asm volatile("cp.async.wait_group %0;\n" :: "n"(n) : "memory")

__device__ __forceinline__ float gelu(float v) {
    return 0.5f * v * (1.f + erff(v * 0.70710678118654752f));
}
__device__ __forceinline__ void ldsm4(uint32_t* r, uint32_t addr) {
    asm volatile("ldmatrix.sync.aligned.m8n8.x4.shared.b16 {%0,%1,%2,%3}, [%4];"
        : "=r"(r[0]), "=r"(r[1]), "=r"(r[2]), "=r"(r[3]) : "r"(addr));
}
__device__ __forceinline__ void mma_bf16(
    float* d, const uint32_t* a, uint32_t b0, uint32_t b1)
{
    asm volatile(
        "mma.sync.aligned.m16n8k16.row.col.f32.bf16.bf16.f32 "
        "{%0,%1,%2,%3}, {%4,%5,%6,%7}, {%8,%9}, {%0,%1,%2,%3};"
        : "+f"(d[0]), "+f"(d[1]), "+f"(d[2]), "+f"(d[3])
        : "r"(a[0]), "r"(a[1]), "r"(a[2]), "r"(a[3]), "r"(b0), "r"(b1));
}

// ---------------------------------------------------------------------------
// k0: g_Wt[n][k] = bf16(W_cat[src(k)][n]) for k<2048 (src skips W2 block)
// ---------------------------------------------------------------------------
__global__ __launch_bounds__(256) void k0_transpose(const float* __restrict__ W)
{
    __shared__ float tile[32][33];
    int k0 = blockIdx.x * 32, n0 = blockIdx.y * 32;
    int tx = threadIdx.x, ty = threadIdx.y;
    #pragma unroll
    for (int j = 0; j < 32; j += 8) {
        int k = k0 + ty + j;
        int src = (k < H) ? k : (k + H);
        tile[ty + j][tx] = W[(size_t)src * H + n0 + tx];
    }
    __syncthreads();
    #pragma unroll
    for (int j = 0; j < 32; j += 8) {
        int n = n0 + ty + j;
        g_Wt[(size_t)n * ZK2 + k0 + tx] = __float2bfloat16(tile[tx][ty + j]);
    }
}

// ---------------------------------------------------------------------------
// kzero: zero pad columns [2085, 2112) of g_Wt  (defensive; also zero-init)
// ---------------------------------------------------------------------------
__global__ __launch_bounds__(256) void kzero()
{
    int idx = blockIdx.x * 256 + threadIdx.x;   // 0 .. 1024*27-1
    if (idx < H * 27) {
        int n = idx / 27, c = idx % 27;
        g_Wt[(size_t)n * ZK2 + 2085 + c] = __float2bfloat16(0.f);
    }
}

// ---------------------------------------------------------------------------
// k_bw2: g_Wt[n][2048+t] = bf16( sum_k bio[t][k] * W_cat[1024+k][n] )
// ---------------------------------------------------------------------------
__global__ __launch_bounds__(256) void k_bw2(
    const float* __restrict__ bio, const float* __restrict__ W)
{
    int n = blockIdx.x * 256 + threadIdx.x;
    int t = blockIdx.y;
    const float* br = bio + (size_t)t * H;
    float acc = 0.f;
    #pragma unroll 8
    for (int k = 0; k < H; k++)
        acc += br[k] * W[(size_t)(H + k) * H + n];
    g_Wt[(size_t)n * ZK2 + 2048 + t] = __float2bfloat16(acc);
}

// ---------------------------------------------------------------------------
// k1: per-warp rows. scores -> softmax -> aware; Z = bf16[h | h*aware | attn]
// 512 threads, 16 warps, 4 rows/warp, grid 256.
// ---------------------------------------------------------------------------
__global__ __launch_bounds__(512) void k1_bio_attn(
    const float* __restrict__ h, const float* __restrict__ bio)
{
    extern __shared__ float bioS[];       // 37*1024 f32
    int tid = threadIdx.x;
    for (int i = tid; i < T*H/4; i += 512)
        ((float4*)bioS)[i] = ((const float4*)bio)[i];
    __syncthreads();

    int wid = tid >> 5, l = tid & 31;
    int row0 = (blockIdx.x * 16 + wid) * 4;
    const float4* bio4 = (const float4*)bioS;

    for (int r = 0; r < 4; r++) {
        int row = row0 + r;
        float4 hr[8];
        const float4* h4 = (const float4*)(h + (size_t)row * H);
        #pragma unroll
        for (int j = 0; j < 8; j++) hr[j] = h4[j*32 + l];

        // scores: all lanes cooperate on each dot; owner lane keeps result
        float v0 = -1e30f, v1 = -1e30f;
        for (int t = 0; t < T; t++) {
            float s = 0.f;
            #pragma unroll
            for (int j = 0; j < 8; j++) {
                float4 b4 = bio4[t*256 + j*32 + l];
                s += hr[j].x*b4.x + hr[j].y*b4.y + hr[j].z*b4.z + hr[j].w*b4.w;
            }
            #pragma unroll
            for (int o = 16; o; o >>= 1) s += __shfl_xor_sync(~0u, s, o);
            s *= 0.03125f;
            if (t < 32) { if (l == t) v0 = s; }
            else        { if (l == t - 32) v1 = s; }
        }

        // softmax (in-warp)
        float mv = fmaxf(v0, (l < T-32) ? v1 : -1e30f);
        #pragma unroll
        for (int o = 16; o; o >>= 1) mv = fmaxf(mv, __shfl_xor_sync(~0u, mv, o));
        float e0 = __expf(v0 - mv);
        float e1 = (l < T-32) ? __expf(v1 - mv) : 0.f;
        float ss = e0 + e1;
        #pragma unroll
        for (int o = 16; o; o >>= 1) ss += __shfl_xor_sync(~0u, ss, o);
        float inv = 1.f / ss;
        e0 *= inv; e1 *= inv;

        // aware = attn @ bio (t uniform per warp -> uniform branch is safe)
        float4 aw[8];
        #pragma unroll
        for (int j = 0; j < 8; j++) aw[j] = make_float4(0.f,0.f,0.f,0.f);
        for (int t = 0; t < T; t++) {
            float a = (t < 32) ? __shfl_sync(~0u, e0, t)
                               : __shfl_sync(~0u, e1, t - 32);
            #pragma unroll
            for (int j = 0; j < 8; j++) {
                float4 b4 = bio4[t*256 + j*32 + l];
                aw[j].x += a*b4.x; aw[j].y += a*b4.y;
                aw[j].z += a*b4.z; aw[j].w += a*b4.w;
            }
        }

        // write Z row (bf16)
        __nv_bfloat16* zr = g_Zb + (size_t)row * ZK2;
        #pragma unroll
        for (int j = 0; j < 8; j++) {
            __nv_bfloat162 p0 = {__float2bfloat16(hr[j].x), __float2bfloat16(hr[j].y)};
            __nv_bfloat162 p1 = {__float2bfloat16(hr[j].z), __float2bfloat16(hr[j].w)};
            uint2 pk = {*(uint32_t*)&p0, *(uint32_t*)&p1};
            *(uint2*)(zr + j*128 + 4*l) = pk;
            __nv_bfloat162 q0 = {__float2bfloat16(hr[j].x*aw[j].x), __float2bfloat16(hr[j].y*aw[j].y)};
            __nv_bfloat162 q1 = {__float2bfloat16(hr[j].z*aw[j].z), __float2bfloat16(hr[j].w*aw[j].w)};
            uint2 qk = {*(uint32_t*)&q0, *(uint32_t*)&q1};
            *(uint2*)(zr + 1024 + j*128 + 4*l) = qk;
        }
        // attn columns (pad to 64 with zeros); per-lane indices -> exec both shfls
        {
            int i0 = 2*l, i1 = 2*l + 1;
            float lo0 = __shfl_sync(~0u, e0, i0 & 31);
            float hi0 = __shfl_sync(~0u, e1, (i0 >= 32) ? (i0 - 32) : 0);
            float lo1 = __shfl_sync(~0u, e0, i1 & 31);
            float hi1 = __shfl_sync(~0u, e1, (i1 >= 32) ? (i1 - 32) : 0);
            float a0 = (i0 < 32) ? lo0 : hi0; if (i0 >= T) a0 = 0.f;
            float a1 = (i1 < 32) ? lo1 : hi1; if (i1 >= T) a1 = 0.f;
            __nv_bfloat162 ap = {__float2bfloat16(a0), __float2bfloat16(a1)};
            *(uint32_t*)(zr + 2048 + 2*l) = *(uint32_t*)&ap;
        }
    }
}

// ---------------------------------------------------------------------------
// k2: Y = gelu(Z @ Wt^T + bc)  bf16 mma.m16n8k16, BM=128 BN=128 BK=64,
// 3-stage cp.async, SW128 swizzle + ldmatrix, 8 warps (4x2), 2 CTAs/SM.
// ---------------------------------------------------------------------------
#define KBM 128
#define KBN 128
#define KBK 64
#define NKI (ZK2/KBK)          // 33
#define STG (KBM*128 + KBN*128)  // 32768 bytes (A 16K + B 16K)
#define SMEM_K2 (3*STG)          // 98304

__device__ __forceinline__ void k2_load_stage(
    uint32_t sb, int tid, int j, const char* Zb, const char* Wb)
{
    uint32_t base = sb + (j % 3) * STG;
    int kb = j * 128;                       // byte offset along K
    #pragma unroll
    for (int q = 0; q < 8; q++) {
        int idx = tid + 256*q;
        if (q < 4) {
            int m = idx >> 3, c = idx & 7;
            cp16(base + ((m*128 + c*16) ^ ((m & 7) << 4)),
                 Zb + (size_t)m * (ZK2*2) + kb + c*16);
        } else {
            int ci = idx - 1024;
            int n = ci >> 3, c = ci & 7;
            cp16(base + 16384 + ((n*128 + c*16) ^ ((n & 7) << 4)),
                 Wb + (size_t)n * (ZK2*2) + kb + c*16);
        }
    }
}

__global__ __launch_bounds__(256, 2) void k2_mma(const float* __restrict__ bc)
{
    extern __shared__ __align__(16) char smem[];
    uint32_t sb = smem_u32(smem);
    int tid = threadIdx.x, lane = tid & 31, wid = tid >> 5;
    int wm = wid & 3, wn = wid >> 2;
    int row0 = blockIdx.y * KBM, n0 = blockIdx.x * KBN;

    const char* Zb = (const char*)g_Zb + (size_t)row0 * (ZK2*2);
    const char* Wb = (const char*)g_Wt + (size_t)n0   * (ZK2*2);

    float acc[2][8][4];
    #pragma unroll
    for (int mt = 0; mt < 2; mt++)
        #pragma unroll
        for (int nt = 0; nt < 8; nt++)
            #pragma unroll
            for (int q = 0; q < 4; q++) acc[mt][nt][q] = 0.f;

    k2_load_stage(sb, tid, 0, Zb, Wb); CP_COMMIT();
    k2_load_stage(sb, tid, 1, Zb, Wb); CP_COMMIT();

    int r15 = lane & 15;
    int hb  = (lane >> 4) << 4;

    for (int i = 0; i < NKI; i++) {
        int j = i + 2;
        if (j < NKI) k2_load_stage(sb, tid, j, Zb, Wb);
        CP_COMMIT();
        CP_WAIT(2);
        __syncthreads();

        uint32_t Ab = sb + (i % 3) * STG;
        uint32_t Bb = Ab + 16384;
        #pragma unroll
        for (int kk = 0; kk < 4; kk++) {
            int kbyte = kk*32 + hb;
            uint32_t a[2][4];
            #pragma unroll
            for (int mt = 0; mt < 2; mt++) {
                int rr = wm*32 + mt*16 + r15;
                ldsm4(a[mt], Ab + rr*128 + (kbyte ^ ((rr & 7) << 4)));
            }
            #pragma unroll
            for (int ntp = 0; ntp < 4; ntp++) {
                int nr = wn*64 + ntp*16 + r15;
                uint32_t b[4];
                ldsm4(b, Bb + nr*128 + (kbyte ^ ((nr & 7) << 4)));
                #pragma unroll
                for (int mt = 0; mt < 2; mt++) {
                    mma_bf16(acc[mt][2*ntp],   a[mt], b[0], b[2]);
                    mma_bf16(acc[mt][2*ntp+1], a[mt], b[1], b[3]);
                }
            }
        }
        __syncthreads();
    }

    // epilogue: bias + GELU -> g_Y (f32)
    int g = lane >> 2, t4 = lane & 3;
    #pragma unroll
    for (int mt = 0; mt < 2; mt++) {
        #pragma unroll
        for (int nt = 0; nt < 8; nt++) {
            int r0 = row0 + wm*32 + mt*16 + g;
            int c  = n0 + wn*64 + nt*8 + 2*t4;
            float b0v = __ldg(bc + c), b1v = __ldg(bc + c + 1);
            float2 o0 = {gelu(acc[mt][nt][0] + b0v), gelu(acc[mt][nt][1] + b1v)};
            float2 o1 = {gelu(acc[mt][nt][2] + b0v), gelu(acc[mt][nt][3] + b1v)};
            *(float2*)(g_Y + (size_t)r0 * H + c) = o0;
            *(float2*)(g_Y + (size_t)(r0 + 8) * H + c) = o1;
        }
    }
}

// ---------------------------------------------------------------------------
// k3: logits = Y @ W_crf + b_crf -> ner_scores (+ -10000 pads). Per-warp rows.
// ---------------------------------------------------------------------------
#define WP3 1028   // smem pitch (floats): f4-aligned, 4-way max bank spread
__global__ __launch_bounds__(512) void k3_crf_proj(
    const float* __restrict__ Wc, const float* __restrict__ bcrf,
    float* __restrict__ out)
{
    extern __shared__ float Ws[];   // [T][WP3]
    int tid = threadIdx.x;
    for (int idx = tid; idx < H*T; idx += 512) {
        int k = idx / T, t = idx % T;
        Ws[t*WP3 + k] = Wc[idx];
    }
    __syncthreads();

    int wid = tid >> 5, l = tid & 31;
    int row0 = (blockIdx.x * 16 + wid) * 4;

    for (int r = 0; r < 4; r++) {
        int row = row0 + r;
        float4 yr[8];
        const float4* y4 = (const float4*)(g_Y + (size_t)row * H);
        #pragma unroll
        for (int j = 0; j < 8; j++) yr[j] = y4[j*32 + l];

        float* orow = out + (size_t)row * LP;
        for (int t = 0; t < T; t++) {
            const float4* w4 = (const float4*)(Ws + t*WP3);
            float s = 0.f;
            #pragma unroll
            for (int j = 0; j < 8; j++) {
                float4 b4 = w4[j*32 + l];
                s += yr[j].x*b4.x + yr[j].y*b4.y + yr[j].z*b4.z + yr[j].w*b4.w;
            }
            #pragma unroll
            for (int o = 16; o; o >>= 1) s += __shfl_xor_sync(~0u, s, o);
            if (l == 0) orow[t] = s + __ldg(bcrf + t);
        }
        if (l == 0) { orow[37] = -10000.f; orow[38] = -10000.f; }
    }
}

// ---------------------------------------------------------------------------
// k4: CRF loglik. One warp per batch; shuffle-only scan.
// ---------------------------------------------------------------------------
__global__ __launch_bounds__(32) void k4_crf(
    const float* __restrict__ scores, const int* __restrict__ labels,
    const int* __restrict__ lens, const float* __restrict__ trans,
    float* __restrict__ loss)
{
    extern __shared__ float sc[];   // S*LP floats
    int b = blockIdx.x;
    int lane = threadIdx.x;
    int len = lens[b];
    const int* lab = labels + b*S;

    {
        uint32_t sbase = smem_u32(sc);
        const float4* src = (const float4*)(scores + (size_t)b * S * LP);
        for (int i = lane; i < S*LP/4; i += 32)
            cp16(sbase + i*16, src + i);
        CP_COMMIT();
        CP_WAIT(0);
        __syncwarp();
    }

    float ET0[LP], ET1[LP], maxT0 = -1e30f, maxT1 = -1e30f;
    {
        const float* tr = trans + lane*LP;
        #pragma unroll
        for (int f = 0; f < LP; f++) maxT0 = fmaxf(maxT0, tr[f]);
        #pragma unroll
        for (int f = 0; f < LP; f++) ET0[f] = __expf(tr[f] - maxT0);
    }
    if (lane < LP-32) {
        const float* tr = trans + (32+lane)*LP;
        #pragma unroll
        for (int f = 0; f < LP; f++) maxT1 = fmaxf(maxT1, tr[f]);
        #pragma unroll
        for (int f = 0; f < LP; f++) ET1[f] = __expf(tr[f] - maxT1);
    }

    float g = 0.f;
    for (int s2 = lane; s2 < len; s2 += 32) g += sc[s2*LP + lab[s2]];
    for (int i = lane; i <= len; i += 32) {
        int frm = (i == 0)   ? T       : lab[i-1];
        int to  = (i == len) ? (T + 1) : lab[i];
        g += trans[to*LP + frm];
    }
    #pragma unroll
    for (int o = 16; o; o >>= 1) g += __shfl_xor_sync(~0u, g, o);

    float a0 = -100.f;
    float a1 = (lane == (T - 32)) ? 0.f : -100.f;

    for (int t = 0; t < len; t++) {
        float v = fmaxf(a0, (lane < LP-32) ? a1 : -1e30f);
        #pragma unroll
        for (int o = 16; o; o >>= 1) v = fmaxf(v, __shfl_xor_sync(~0u, v, o));
        float e0 = __expf(a0 - v);
        float e1 = (lane < LP-32) ? __expf(a1 - v) : 0.f;
        float s0a = 0.f, s0b = 0.f, s1a = 0.f, s1b = 0.f;
        #pragma unroll
        for (int f = 0; f < 32; f += 2) {
            float ea = __shfl_sync(~0u, e0, f);
            float eb = __shfl_sync(~0u, e0, f+1);
            s0a += ea*ET0[f];   s0b += eb*ET0[f+1];
            s1a += ea*ET1[f];   s1b += eb*ET1[f+1];
        }
        #pragma unroll
        for (int f = 0; f < LP-32; f++) {
            float ea = __shfl_sync(~0u, e1, f);
            s0a += ea*ET0[32+f];
            s1a += ea*ET1[32+f];
        }
        a0 = sc[t*LP + lane] + v + maxT0 + __logf(s0a + s0b);
        if (lane < LP-32)
            a1 = sc[t*LP + 32 + lane] + v + maxT1 + __logf(s1a + s1b);
    }

    a0 += trans[(T+1)*LP + lane];
    if (lane < LP-32) a1 += trans[(T+1)*LP + 32 + lane];
    float v = fmaxf(a0, (lane < LP-32) ? a1 : -1e30f);
    #pragma unroll
    for (int o = 16; o; o >>= 1) v = fmaxf(v, __shfl_xor_sync(~0u, v, o));
    float e = __expf(a0 - v) + ((lane < LP-32) ? __expf(a1 - v) : 0.f);
    #pragma unroll
    for (int o = 16; o; o >>= 1) e += __shfl_xor_sync(~0u, e, o);
    if (lane == 0) loss[b] = g - (v + logf(e));
}

// ---------------------------------------------------------------------------
extern "C" void kernel_launch(void* const* d_in, const int* in_sizes, int n_in,
                              void* d_out, int out_size)
{
    const float* h      = (const float*)d_in[0];
    const int*   lens   = (const int*)d_in[2];
    const int*   labels = (const int*)d_in[3];
    const float* bio    = (const float*)d_in[4];
    const float* W_cat  = (const float*)d_in[5];
    const float* b_cat  = (const float*)d_in[6];
    const float* W_crf  = (const float*)d_in[7];
    const float* b_crf  = (const float*)d_in[8];
    const float* trans  = (const float*)d_in[9];

    float* out = (float*)d_out;            // ner_scores [B,S,LP] then loss [B]
    float* loss = out + (size_t)B * S * LP;

    size_t smem1 = (size_t)(T*H) * sizeof(float);       // 151552
    size_t smem3 = (size_t)(T*WP3) * sizeof(float);     // 152144
    size_t smem4 = (size_t)(S*LP) * sizeof(float);      // 79872

    static int attr_done = 0;
    if (!attr_done) {
        cudaFuncSetAttribute(k1_bio_attn, cudaFuncAttributeMaxDynamicSharedMemorySize, (int)smem1);
        cudaFuncSetAttribute(k2_mma,      cudaFuncAttributeMaxDynamicSharedMemorySize, SMEM_K2);
        cudaFuncSetAttribute(k3_crf_proj, cudaFuncAttributeMaxDynamicSharedMemorySize, (int)smem3);
        cudaFuncSetAttribute(k4_crf,      cudaFuncAttributeMaxDynamicSharedMemorySize, (int)smem4);
        attr_done = 1;
    }

    k0_transpose<<<dim3(2048/32, H/32), dim3(32, 8)>>>(W_cat);
    kzero<<<(H*27 + 255)/256, 256>>>();
    k_bw2<<<dim3(H/256, T), 256>>>(bio, W_cat);
    k1_bio_attn<<<BS/64, 512, smem1>>>(h, bio);
    k2_mma<<<dim3(H/KBN, BS/KBM), 256, SMEM_K2>>>(b_cat);
    k3_crf_proj<<<BS/64, 512, smem3>>>(W_crf, b_crf, out);
    k4_crf<<<B, 32, smem4>>>(out, labels, lens, trans, loss);
}